// round 16
// baseline (speedup 1.0000x reference)
#include <cuda_runtime.h>
#include <cuda_bf16.h>
#include <math.h>
#include <stdint.h>

#define BATCH   4096
#define HIDDEN  4096
#define LATENT  20480
#define TAILC   128
#define KIN     (LATENT + TAILC)   // 20608

// Scratch (allocation-free rule: __device__ globals)
__device__ __align__(16) float g_tail[BATCH * TAILC];
__device__ __align__(16) float g_a0[(size_t)BATCH * HIDDEN];
__device__ __align__(16) float g_a1[(size_t)BATCH * HIDDEN];

// ---------------------------------------------------------------------------
// Helpers (baseline ISA only: ldmatrix + mma.sync, both sm_80+)
// ---------------------------------------------------------------------------
__device__ __forceinline__ uint32_t smem_u32(const void* p) {
    uint32_t a;
    asm("{ .reg .u64 t; cvta.to.shared.u64 t, %1; cvt.u32.u64 %0, t; }"
        : "=r"(a) : "l"(p));
    return a;
}

__device__ __forceinline__ void ldsm4(uint32_t* r, uint32_t addr) {
    asm volatile("ldmatrix.sync.aligned.m8n8.x4.shared.b16 {%0,%1,%2,%3}, [%4];"
                 : "=r"(r[0]), "=r"(r[1]), "=r"(r[2]), "=r"(r[3]) : "r"(addr));
}

__device__ __forceinline__ void mma16816(float* d, const uint32_t* a, const uint32_t* b) {
    asm volatile(
        "mma.sync.aligned.m16n8k16.row.col.f32.bf16.bf16.f32 "
        "{%0,%1,%2,%3}, {%4,%5,%6,%7}, {%8,%9}, {%0,%1,%2,%3};"
        : "+f"(d[0]), "+f"(d[1]), "+f"(d[2]), "+f"(d[3])
        : "r"(a[0]), "r"(a[1]), "r"(a[2]), "r"(a[3]), "r"(b[0]), "r"(b[1]));
}

// split fp32x4 into bf16 hi/lo x4 (hi = rn(v), lo = rn(v - hi)), store 8B each
__device__ __forceinline__ void split_store(float4 v, char* hi, char* lo, int off) {
    __nv_bfloat162 h01 = __floats2bfloat162_rn(v.x, v.y);
    __nv_bfloat162 h23 = __floats2bfloat162_rn(v.z, v.w);
    float2 f01 = __bfloat1622float2(h01);
    float2 f23 = __bfloat1622float2(h23);
    __nv_bfloat162 l01 = __floats2bfloat162_rn(v.x - f01.x, v.y - f01.y);
    __nv_bfloat162 l23 = __floats2bfloat162_rn(v.z - f23.x, v.w - f23.y);
    *reinterpret_cast<uint2*>(hi + off) =
        make_uint2(*reinterpret_cast<uint32_t*>(&h01), *reinterpret_cast<uint32_t*>(&h23));
    *reinterpret_cast<uint2*>(lo + off) =
        make_uint2(*reinterpret_cast<uint32_t*>(&l01), *reinterpret_cast<uint32_t*>(&l23));
}

// ---------------------------------------------------------------------------
// Prep: time MLP + digit embedding -> g_tail[B,128]
// ---------------------------------------------------------------------------
__global__ void prep_kernel(const int* __restrict__ timesteps,
                            const int* __restrict__ digits,
                            const int* __restrict__ num_steps,
                            const float* __restrict__ emb,
                            const float* __restrict__ tw0,
                            const float* __restrict__ tb0,
                            const float* __restrict__ tw1,
                            const float* __restrict__ tb1) {
    __shared__ float h[64];
    const int b = blockIdx.x;
    const int i = threadIdx.x;

    const float denom = fmaxf((float)(num_steps[0] - 1), 1.0f);
    const float t = (float)timesteps[b] / denom;
    const float PI = 3.14159265358979323846f;

    float acc = tb0[i]
              + tw0[i * 4 + 0] * t
              + tw0[i * 4 + 1] * (t * t)
              + tw0[i * 4 + 2] * sinf(PI * t)
              + tw0[i * 4 + 3] * cosf(PI * t);
    h[i] = fmaxf(acc, 0.0f);
    __syncthreads();

    float acc2 = tb1[i];
#pragma unroll
    for (int k = 0; k < 64; k++) acc2 += tw1[i * 64 + k] * h[k];

    g_tail[b * TAILC + 64 + i] = acc2;
    g_tail[b * TAILC + i]      = emb[digits[b] * 64 + i];
}

// ---------------------------------------------------------------------------
// HMMA bf16x3 GEMM:  C[M,N] = act( A[M,K](fp32) @ W[N,K](fp32)^T + bias )
// BM=BN=128, BK=64. 8 warps (4x2), warp tile 32x64.
// Smem: bf16 hi/lo tiles, row stride 144B (pad) -> ldmatrix conflict-free.
// ---------------------------------------------------------------------------
#define RSB     144                 // row stride bytes (64 bf16 = 128B + 16 pad)
#define TILE_B  (128 * RSB)         // 18432
#define STAGE_B (4 * TILE_B)        // A_hi, A_lo, B_hi, B_lo = 73728
#define SMEM_B  (2 * STAGE_B)       // 147456

template<bool RELU, bool SPLIT>
__global__ __launch_bounds__(256, 1)
void gemm_hmma(const float* __restrict__ A,
               const float* __restrict__ A2,
               const float* __restrict__ W,
               const float* __restrict__ bias,
               float* __restrict__ C,
               int M, int N, int K, int LDA, int K0) {
    extern __shared__ __align__(16) char sm[];
    __shared__ float s_bias[128];

    // CTA swizzle for L2 reuse
    const int grid_m = M / 128;
    const int grid_n = N / 128;
    const int GROUP  = 16;
    const int pid    = blockIdx.x;
    const int width  = GROUP * grid_n;
    const int group  = pid / width;
    const int first_m = group * GROUP;
    const int gsz     = min(grid_m - first_m, GROUP);
    const int mt = first_m + (pid % gsz);
    const int nt = (pid % width) / gsz;
    const int m0 = mt * 128;
    const int n0 = nt * 128;

    const int tid    = threadIdx.x;
    const int wid    = tid >> 5;
    const int lane   = tid & 31;
    const int warp_m = wid & 3;   // 4 warps along M (32 rows each)
    const int warp_n = wid >> 2;  // 2 warps along N (64 cols each)

    if (tid < 128) s_bias[tid] = bias[n0 + tid];

    const uint32_t smbase = smem_u32(sm);

    // per-lane constant parts of ldmatrix addresses (within a tile region)
    const uint32_t aoff = (uint32_t)(warp_m * 32 + (lane & 15)) * RSB + ((lane >> 4) << 4);
    const uint32_t boff = (uint32_t)(warp_n * 64 + ((lane >> 4) << 3) + (lane & 7)) * RSB
                        + (((lane >> 3) & 1) << 4);

    float acc[2][8][4];
#pragma unroll
    for (int i = 0; i < 2; i++)
#pragma unroll
        for (int j = 0; j < 8; j++)
#pragma unroll
            for (int q = 0; q < 4; q++) acc[i][j][q] = 0.0f;

    const int nch = K / 64;
    float4 ra[8], rb[8];

    // loader index mapping: idx = i*256 + tid; row = idx>>4 (0..127), q = idx&15
    auto LOAD = [&](int c) {
        const int kc = c * 64;
        const float* Ab;
        int lda;
        if (SPLIT && kc >= K0) { Ab = A2 + (kc - K0); lda = TAILC; }
        else                   { Ab = A + kc;         lda = LDA;  }
#pragma unroll
        for (int i = 0; i < 8; i++) {
            const int idx = i * 256 + tid;
            const int row = idx >> 4, q = idx & 15;
            ra[i] = *reinterpret_cast<const float4*>(Ab + (size_t)(m0 + row) * lda + q * 4);
            rb[i] = *reinterpret_cast<const float4*>(W + (size_t)(n0 + row) * K + kc + q * 4);
        }
    };

    auto STORE = [&](int buf) {
        char* sa_hi = sm + buf * STAGE_B;
        char* sa_lo = sa_hi + TILE_B;
        char* sb_hi = sa_hi + 2 * TILE_B;
        char* sb_lo = sa_hi + 3 * TILE_B;
#pragma unroll
        for (int i = 0; i < 8; i++) {
            const int idx = i * 256 + tid;
            const int row = idx >> 4, q = idx & 15;
            const int off = row * RSB + q * 8;
            split_store(ra[i], sa_hi, sa_lo, off);
            split_store(rb[i], sb_hi, sb_lo, off);
        }
    };

    LOAD(0);
    STORE(0);
    __syncthreads();

    for (int c = 0; c < nch; c++) {
        if (c + 1 < nch) LOAD(c + 1);

        const uint32_t stage = smbase + (uint32_t)(c & 1) * STAGE_B;
        const uint32_t sa_hi = stage;
        const uint32_t sa_lo = stage + TILE_B;
        const uint32_t sb_hi = stage + 2 * TILE_B;
        const uint32_t sb_lo = stage + 3 * TILE_B;

#pragma unroll
        for (int ks = 0; ks < 4; ks++) {
            const uint32_t kb = ks * 32;  // 16 bf16 = 32 bytes per k-step
            uint32_t ah[2][4], al[2][4];
#pragma unroll
            for (int mtile = 0; mtile < 2; mtile++) {
                const uint32_t ao = aoff + mtile * (16 * RSB) + kb;
                ldsm4(ah[mtile], sa_hi + ao);
                ldsm4(al[mtile], sa_lo + ao);
            }
#pragma unroll
            for (int p = 0; p < 4; p++) {       // pairs of 8-col n-tiles
                uint32_t bh[4], bl[4];
                const uint32_t bo = boff + p * (16 * RSB) + kb;
                ldsm4(bh, sb_hi + bo);
                ldsm4(bl, sb_lo + bo);
#pragma unroll
                for (int mtile = 0; mtile < 2; mtile++) {
                    mma16816(acc[mtile][p * 2],     ah[mtile], bh);
                    mma16816(acc[mtile][p * 2 + 1], ah[mtile], bh + 2);
                    mma16816(acc[mtile][p * 2],     ah[mtile], bl);
                    mma16816(acc[mtile][p * 2 + 1], ah[mtile], bl + 2);
                    mma16816(acc[mtile][p * 2],     al[mtile], bh);
                    mma16816(acc[mtile][p * 2 + 1], al[mtile], bh + 2);
                }
            }
        }

        if (c + 1 < nch) STORE((c + 1) & 1);
        __syncthreads();
    }

    // Epilogue: c0,c1 -> (row, col..col+1); c2,c3 -> (row+8, col..col+1)
    const int row_b = m0 + warp_m * 32 + (lane >> 2);
    const int col_l = warp_n * 64 + (lane & 3) * 2;   // within 128-col tile
#pragma unroll
    for (int mtile = 0; mtile < 2; mtile++) {
#pragma unroll
        for (int ntile = 0; ntile < 8; ntile++) {
            const int cl = col_l + ntile * 8;
            const float b0 = s_bias[cl], b1 = s_bias[cl + 1];
            float v0 = acc[mtile][ntile][0] + b0;
            float v1 = acc[mtile][ntile][1] + b1;
            float v2 = acc[mtile][ntile][2] + b0;
            float v3 = acc[mtile][ntile][3] + b1;
            if (RELU) {
                v0 = fmaxf(v0, 0.0f); v1 = fmaxf(v1, 0.0f);
                v2 = fmaxf(v2, 0.0f); v3 = fmaxf(v3, 0.0f);
            }
            const int r0 = row_b + mtile * 16;
            float* p0 = C + (size_t)r0 * N + n0 + cl;
            float* p1 = C + (size_t)(r0 + 8) * N + n0 + cl;
            *reinterpret_cast<float2*>(p0) = make_float2(v0, v1);
            *reinterpret_cast<float2*>(p1) = make_float2(v2, v3);
        }
    }
}

// ---------------------------------------------------------------------------
// kernel_launch
// ---------------------------------------------------------------------------
extern "C" void kernel_launch(void* const* d_in, const int* in_sizes, int n_in,
                              void* d_out, int out_size) {
    const float* noisy     = (const float*)d_in[0];
    const int*   digits    = (const int*)  d_in[1];
    const int*   timesteps = (const int*)  d_in[2];
    const int*   num_steps = (const int*)  d_in[3];
    const float* emb       = (const float*)d_in[4];
    const float* tw0       = (const float*)d_in[5];
    const float* tb0       = (const float*)d_in[6];
    const float* tw1       = (const float*)d_in[7];
    const float* tb1       = (const float*)d_in[8];
    const float* nw0       = (const float*)d_in[9];
    const float* nb0       = (const float*)d_in[10];
    const float* nw1       = (const float*)d_in[11];
    const float* nb1       = (const float*)d_in[12];
    const float* nw2       = (const float*)d_in[13];
    const float* nb2       = (const float*)d_in[14];
    float* out = (float*)d_out;

    float *tailp, *a0p, *a1p;
    cudaGetSymbolAddress((void**)&tailp, g_tail);
    cudaGetSymbolAddress((void**)&a0p,   g_a0);
    cudaGetSymbolAddress((void**)&a1p,   g_a1);

    cudaFuncSetAttribute(gemm_hmma<true, true>,
                         cudaFuncAttributeMaxDynamicSharedMemorySize, SMEM_B);
    cudaFuncSetAttribute(gemm_hmma<true, false>,
                         cudaFuncAttributeMaxDynamicSharedMemorySize, SMEM_B);
    cudaFuncSetAttribute(gemm_hmma<false, false>,
                         cudaFuncAttributeMaxDynamicSharedMemorySize, SMEM_B);

    prep_kernel<<<BATCH, 64>>>(timesteps, digits, num_steps, emb, tw0, tb0, tw1, tb1);

    // GEMM0: a0 = relu([x|tail] @ nw0^T + nb0)   M=4096 N=4096 K=20608
    gemm_hmma<true, true><<<(BATCH / 128) * (HIDDEN / 128), 256, SMEM_B>>>(
        noisy, tailp, nw0, nb0, a0p, BATCH, HIDDEN, KIN, LATENT, LATENT);

    // GEMM1: a1 = relu(a0 @ nw1^T + nb1)         M=4096 N=4096 K=4096
    gemm_hmma<true, false><<<(BATCH / 128) * (HIDDEN / 128), 256, SMEM_B>>>(
        a0p, nullptr, nw1, nb1, a1p, BATCH, HIDDEN, HIDDEN, HIDDEN, HIDDEN);

    // GEMM2: out = a1 @ nw2^T + nb2              M=4096 N=20480 K=4096
    gemm_hmma<false, false><<<(BATCH / 128) * (LATENT / 128), 256, SMEM_B>>>(
        a1p, nullptr, nw2, nb2, out, BATCH, LATENT, HIDDEN, HIDDEN, HIDDEN);
}

// round 17
// speedup vs baseline: 1.0451x; 1.0451x over previous
#include <cuda_runtime.h>
#include <cuda_bf16.h>
#include <math.h>
#include <stdint.h>

#define BATCH   4096
#define HIDDEN  4096
#define LATENT  20480
#define TAILC   128
#define KIN     (LATENT + TAILC)   // 20608

// ---------------------------------------------------------------------------
// Scratch (allocation-free rule: __device__ globals)
// bf16 hi/lo pre-split copies of all GEMM operands.
// ---------------------------------------------------------------------------
__device__ __align__(16) __nv_bfloat16 g_xhi[(size_t)BATCH * LATENT];
__device__ __align__(16) __nv_bfloat16 g_xlo[(size_t)BATCH * LATENT];
__device__ __align__(16) __nv_bfloat16 g_thi[BATCH * TAILC];
__device__ __align__(16) __nv_bfloat16 g_tlo[BATCH * TAILC];
__device__ __align__(16) __nv_bfloat16 g_w0hi[(size_t)HIDDEN * KIN];
__device__ __align__(16) __nv_bfloat16 g_w0lo[(size_t)HIDDEN * KIN];
__device__ __align__(16) __nv_bfloat16 g_w1hi[(size_t)HIDDEN * HIDDEN];
__device__ __align__(16) __nv_bfloat16 g_w1lo[(size_t)HIDDEN * HIDDEN];
__device__ __align__(16) __nv_bfloat16 g_w2hi[(size_t)LATENT * HIDDEN];
__device__ __align__(16) __nv_bfloat16 g_w2lo[(size_t)LATENT * HIDDEN];
__device__ __align__(16) __nv_bfloat16 g_a0hi[(size_t)BATCH * HIDDEN];
__device__ __align__(16) __nv_bfloat16 g_a0lo[(size_t)BATCH * HIDDEN];
__device__ __align__(16) __nv_bfloat16 g_a1hi[(size_t)BATCH * HIDDEN];
__device__ __align__(16) __nv_bfloat16 g_a1lo[(size_t)BATCH * HIDDEN];

// ---------------------------------------------------------------------------
// Helpers (baseline ISA: ldmatrix + mma.sync + cp.async, all sm_80+)
// ---------------------------------------------------------------------------
__device__ __forceinline__ uint32_t smem_u32(const void* p) {
    uint32_t a;
    asm("{ .reg .u64 t; cvta.to.shared.u64 t, %1; cvt.u32.u64 %0, t; }"
        : "=r"(a) : "l"(p));
    return a;
}

__device__ __forceinline__ void ldsm4(uint32_t* r, uint32_t addr) {
    asm volatile("ldmatrix.sync.aligned.m8n8.x4.shared.b16 {%0,%1,%2,%3}, [%4];"
                 : "=r"(r[0]), "=r"(r[1]), "=r"(r[2]), "=r"(r[3]) : "r"(addr));
}

__device__ __forceinline__ void mma16816(float* d, const uint32_t* a, const uint32_t* b) {
    asm volatile(
        "mma.sync.aligned.m16n8k16.row.col.f32.bf16.bf16.f32 "
        "{%0,%1,%2,%3}, {%4,%5,%6,%7}, {%8,%9}, {%0,%1,%2,%3};"
        : "+f"(d[0]), "+f"(d[1]), "+f"(d[2]), "+f"(d[3])
        : "r"(a[0]), "r"(a[1]), "r"(a[2]), "r"(a[3]), "r"(b[0]), "r"(b[1]));
}

#define CP16(dst, src) \
    asm volatile("cp.async.cg.shared.global [%0], [%1], 16;" \
                 :: "r"(dst), "l"(src) : "memory")
#define CP_COMMIT()  asm volatile("cp.async.commit_group;" ::: "memory")
#define CP_WAIT1()   asm volatile("cp.async.wait_group 1;" ::: "memory")

// ---------------------------------------------------------------------------
// fp32 -> bf16 hi/lo split (grid-stride, vectorized)
// ---------------------------------------------------------------------------
__global__ void split_f32(const float4* __restrict__ src,
                          uint2* __restrict__ hi, uint2* __restrict__ lo, int n4) {
    for (int i = blockIdx.x * blockDim.x + threadIdx.x; i < n4;
         i += gridDim.x * blockDim.x) {
        float4 v = src[i];
        __nv_bfloat162 h01 = __floats2bfloat162_rn(v.x, v.y);
        __nv_bfloat162 h23 = __floats2bfloat162_rn(v.z, v.w);
        float2 f01 = __bfloat1622float2(h01);
        float2 f23 = __bfloat1622float2(h23);
        __nv_bfloat162 l01 = __floats2bfloat162_rn(v.x - f01.x, v.y - f01.y);
        __nv_bfloat162 l23 = __floats2bfloat162_rn(v.z - f23.x, v.w - f23.y);
        hi[i] = make_uint2(*reinterpret_cast<uint32_t*>(&h01),
                           *reinterpret_cast<uint32_t*>(&h23));
        lo[i] = make_uint2(*reinterpret_cast<uint32_t*>(&l01),
                           *reinterpret_cast<uint32_t*>(&l23));
    }
}

// ---------------------------------------------------------------------------
// Prep: time MLP + digit embedding -> g_thi/g_tlo [B,128] (bf16 hi/lo)
// ---------------------------------------------------------------------------
__global__ void prep_kernel(const int* __restrict__ timesteps,
                            const int* __restrict__ digits,
                            const int* __restrict__ num_steps,
                            const float* __restrict__ emb,
                            const float* __restrict__ tw0,
                            const float* __restrict__ tb0,
                            const float* __restrict__ tw1,
                            const float* __restrict__ tb1) {
    __shared__ float h[64];
    const int b = blockIdx.x;
    const int i = threadIdx.x;

    const float denom = fmaxf((float)(num_steps[0] - 1), 1.0f);
    const float t = (float)timesteps[b] / denom;
    const float PI = 3.14159265358979323846f;

    float acc = tb0[i]
              + tw0[i * 4 + 0] * t
              + tw0[i * 4 + 1] * (t * t)
              + tw0[i * 4 + 2] * sinf(PI * t)
              + tw0[i * 4 + 3] * cosf(PI * t);
    h[i] = fmaxf(acc, 0.0f);
    __syncthreads();

    float acc2 = tb1[i];
#pragma unroll
    for (int k = 0; k < 64; k++) acc2 += tw1[i * 64 + k] * h[k];

    const float cond = emb[digits[b] * 64 + i];

    __nv_bfloat16 th = __float2bfloat16_rn(acc2);
    __nv_bfloat16 tl = __float2bfloat16_rn(acc2 - __bfloat162float(th));
    __nv_bfloat16 ch = __float2bfloat16_rn(cond);
    __nv_bfloat16 cl = __float2bfloat16_rn(cond - __bfloat162float(ch));
    g_thi[b * TAILC + 64 + i] = th;  g_tlo[b * TAILC + 64 + i] = tl;
    g_thi[b * TAILC + i]      = ch;  g_tlo[b * TAILC + i]      = cl;
}

// ---------------------------------------------------------------------------
// HMMA bf16x3 GEMM:  C[M,N] = act( (Ahi+Alo) @ (Whi+Wlo)^T + bias )
// CTA: 128 threads (4 warps, 2x2), BM=BN=128, BK=32, warp tile 64x64.
// cp.async 2-stage pipeline, 80KB smem -> 2 CTAs/SM.
// Smem rows: 32 bf16 = 64B + 16B pad = 80B stride (ldsm conflict-free).
// ---------------------------------------------------------------------------
#define RSB     80
#define TILE_SB (128 * RSB)        // 10240  (one of Ahi/Alo/Bhi/Blo)
#define STAGE_B (4 * TILE_SB)      // 40960
#define SMEM_B  (2 * STAGE_B)      // 81920

template<bool RELU, bool SPLIT, bool OUTBF16>
__global__ __launch_bounds__(128, 2)
void gemm_hmma(const __nv_bfloat16* __restrict__ Ahi,
               const __nv_bfloat16* __restrict__ Alo,
               const __nv_bfloat16* __restrict__ AThi,
               const __nv_bfloat16* __restrict__ ATlo,
               const __nv_bfloat16* __restrict__ Whi,
               const __nv_bfloat16* __restrict__ Wlo,
               const float* __restrict__ bias,
               float* __restrict__ Cf,
               __nv_bfloat16* __restrict__ Chi,
               __nv_bfloat16* __restrict__ Clo,
               int M, int N, int K, int LDA, int K0) {
    extern __shared__ __align__(16) char sm[];
    __shared__ float s_bias[128];

    // CTA swizzle for L2 reuse
    const int grid_m = M / 128;
    const int grid_n = N / 128;
    const int GROUP  = 16;
    const int pid    = blockIdx.x;
    const int width  = GROUP * grid_n;
    const int group  = pid / width;
    const int first_m = group * GROUP;
    const int gsz     = min(grid_m - first_m, GROUP);
    const int mt_  = first_m + (pid % gsz);
    const int nt_  = (pid % width) / gsz;
    const int m0 = mt_ * 128;
    const int n0 = nt_ * 128;

    const int tid    = threadIdx.x;
    const int wid    = tid >> 5;
    const int lane   = tid & 31;
    const int warp_m = wid & 1;   // 2 warps along M (64 rows each)
    const int warp_n = wid >> 1;  // 2 warps along N (64 cols each)

    s_bias[tid] = bias[n0 + tid];

    const uint32_t smbase = smem_u32(sm);

    // ldmatrix lane-address components (within a tile region)
    const uint32_t aoff = (uint32_t)(warp_m * 64 + (lane & 15)) * RSB + ((lane >> 4) << 4);
    const uint32_t boff = (uint32_t)(warp_n * 64 + ((lane >> 4) << 3) + (lane & 7)) * RSB
                        + (((lane >> 3) & 1) << 4);

    float acc[4][8][4];
#pragma unroll
    for (int i = 0; i < 4; i++)
#pragma unroll
        for (int j = 0; j < 8; j++)
#pragma unroll
            for (int q = 0; q < 4; q++) acc[i][j][q] = 0.0f;

    const int nch = K / 32;
    const int pr = tid >> 2;   // prefetch row-within-32  (0..31)
    const int pq = tid & 3;    // prefetch 16B quad       (0..3)

    auto PREFETCH = [&](int c) {
        if (c < nch) {
            const int kc = c * 32;
            const __nv_bfloat16 *pah, *pal;
            int lda, kcol;
            if (SPLIT && kc >= K0) { pah = AThi; pal = ATlo; lda = TAILC; kcol = kc - K0; }
            else                   { pah = Ahi;  pal = Alo;  lda = LDA;   kcol = kc; }
            const uint32_t s0 = smbase + (uint32_t)(c & 1) * STAGE_B;
#pragma unroll
            for (int rr = 0; rr < 4; rr++) {
                const int row  = rr * 32 + pr;
                const uint32_t doff = row * RSB + pq * 16;
                const char* sah = (const char*)(pah + (size_t)(m0 + row) * lda + kcol) + pq * 16;
                const char* sal = (const char*)(pal + (size_t)(m0 + row) * lda + kcol) + pq * 16;
                const char* sbh = (const char*)(Whi + (size_t)(n0 + row) * K + kc) + pq * 16;
                const char* sbl = (const char*)(Wlo + (size_t)(n0 + row) * K + kc) + pq * 16;
                CP16(s0 + 0 * TILE_SB + doff, sah);
                CP16(s0 + 1 * TILE_SB + doff, sal);
                CP16(s0 + 2 * TILE_SB + doff, sbh);
                CP16(s0 + 3 * TILE_SB + doff, sbl);
            }
        }
        CP_COMMIT();   // always commit (keeps group accounting exact)
    };

    PREFETCH(0);
    PREFETCH(1);

    for (int c = 0; c < nch; c++) {
        CP_WAIT1();          // chunk c's group retired
        __syncthreads();     // cross-thread visibility

        const uint32_t st = smbase + (uint32_t)(c & 1) * STAGE_B;
        const uint32_t sa_hi = st;
        const uint32_t sa_lo = st + TILE_SB;
        const uint32_t sb_hi = st + 2 * TILE_SB;
        const uint32_t sb_lo = st + 3 * TILE_SB;

#pragma unroll
        for (int ks = 0; ks < 2; ks++) {
            const uint32_t kb = ks * 32;      // 16 bf16 = 32B per k-step
            uint32_t ahf[4][4], alf[4][4];
#pragma unroll
            for (int mt = 0; mt < 4; mt++) {
                const uint32_t ao = aoff + mt * (16 * RSB) + kb;
                ldsm4(ahf[mt], sa_hi + ao);
                ldsm4(alf[mt], sa_lo + ao);
            }
#pragma unroll
            for (int p = 0; p < 4; p++) {
                uint32_t bh[4], bl[4];
                const uint32_t bo = boff + p * (16 * RSB) + kb;
                ldsm4(bh, sb_hi + bo);
                ldsm4(bl, sb_lo + bo);
                // 24 MMAs, >=8 independent between same-acc writes
#pragma unroll
                for (int mt = 0; mt < 4; mt++) {
                    mma16816(acc[mt][p * 2],     ahf[mt], bh);
                    mma16816(acc[mt][p * 2 + 1], ahf[mt], bh + 2);
                }
#pragma unroll
                for (int mt = 0; mt < 4; mt++) {
                    mma16816(acc[mt][p * 2],     ahf[mt], bl);
                    mma16816(acc[mt][p * 2 + 1], ahf[mt], bl + 2);
                }
#pragma unroll
                for (int mt = 0; mt < 4; mt++) {
                    mma16816(acc[mt][p * 2],     alf[mt], bh);
                    mma16816(acc[mt][p * 2 + 1], alf[mt], bh + 2);
                }
            }
        }

        __syncthreads();     // all warps done reading buf (c&1)
        PREFETCH(c + 2);     // refill it
    }

    // Epilogue
    const int row_w = m0 + warp_m * 64 + (lane >> 2);
    const int col_b = warp_n * 64 + (lane & 3) * 2;   // tile-local col
#pragma unroll
    for (int mt = 0; mt < 4; mt++) {
#pragma unroll
        for (int nt = 0; nt < 8; nt++) {
            const int cl = col_b + nt * 8;
            const float b0 = s_bias[cl], b1 = s_bias[cl + 1];
            float v0 = acc[mt][nt][0] + b0;
            float v1 = acc[mt][nt][1] + b1;
            float v2 = acc[mt][nt][2] + b0;
            float v3 = acc[mt][nt][3] + b1;
            if (RELU) {
                v0 = fmaxf(v0, 0.0f); v1 = fmaxf(v1, 0.0f);
                v2 = fmaxf(v2, 0.0f); v3 = fmaxf(v3, 0.0f);
            }
            const int r0 = row_w + mt * 16;
            const size_t o0 = (size_t)r0 * N + n0 + cl;
            const size_t o1 = (size_t)(r0 + 8) * N + n0 + cl;
            if (OUTBF16) {
                __nv_bfloat162 h01 = __floats2bfloat162_rn(v0, v1);
                __nv_bfloat162 h23 = __floats2bfloat162_rn(v2, v3);
                float2 f01 = __bfloat1622float2(h01);
                float2 f23 = __bfloat1622float2(h23);
                __nv_bfloat162 l01 = __floats2bfloat162_rn(v0 - f01.x, v1 - f01.y);
                __nv_bfloat162 l23 = __floats2bfloat162_rn(v2 - f23.x, v3 - f23.y);
                *reinterpret_cast<__nv_bfloat162*>(Chi + o0) = h01;
                *reinterpret_cast<__nv_bfloat162*>(Clo + o0) = l01;
                *reinterpret_cast<__nv_bfloat162*>(Chi + o1) = h23;
                *reinterpret_cast<__nv_bfloat162*>(Clo + o1) = l23;
            } else {
                *reinterpret_cast<float2*>(Cf + o0) = make_float2(v0, v1);
                *reinterpret_cast<float2*>(Cf + o1) = make_float2(v2, v3);
            }
        }
    }
}

// ---------------------------------------------------------------------------
// kernel_launch
// ---------------------------------------------------------------------------
extern "C" void kernel_launch(void* const* d_in, const int* in_sizes, int n_in,
                              void* d_out, int out_size) {
    const float* noisy     = (const float*)d_in[0];
    const int*   digits    = (const int*)  d_in[1];
    const int*   timesteps = (const int*)  d_in[2];
    const int*   num_steps = (const int*)  d_in[3];
    const float* emb       = (const float*)d_in[4];
    const float* tw0       = (const float*)d_in[5];
    const float* tb0       = (const float*)d_in[6];
    const float* tw1       = (const float*)d_in[7];
    const float* tb1       = (const float*)d_in[8];
    const float* nw0       = (const float*)d_in[9];
    const float* nb0       = (const float*)d_in[10];
    const float* nw1       = (const float*)d_in[11];
    const float* nb1       = (const float*)d_in[12];
    const float* nw2       = (const float*)d_in[13];
    const float* nb2       = (const float*)d_in[14];
    float* out = (float*)d_out;

    __nv_bfloat16 *xhi, *xlo, *thi, *tlo, *w0hi, *w0lo, *w1hi, *w1lo, *w2hi, *w2lo;
    __nv_bfloat16 *a0hi, *a0lo, *a1hi, *a1lo;
    cudaGetSymbolAddress((void**)&xhi,  g_xhi);
    cudaGetSymbolAddress((void**)&xlo,  g_xlo);
    cudaGetSymbolAddress((void**)&thi,  g_thi);
    cudaGetSymbolAddress((void**)&tlo,  g_tlo);
    cudaGetSymbolAddress((void**)&w0hi, g_w0hi);
    cudaGetSymbolAddress((void**)&w0lo, g_w0lo);
    cudaGetSymbolAddress((void**)&w1hi, g_w1hi);
    cudaGetSymbolAddress((void**)&w1lo, g_w1lo);
    cudaGetSymbolAddress((void**)&w2hi, g_w2hi);
    cudaGetSymbolAddress((void**)&w2lo, g_w2lo);
    cudaGetSymbolAddress((void**)&a0hi, g_a0hi);
    cudaGetSymbolAddress((void**)&a0lo, g_a0lo);
    cudaGetSymbolAddress((void**)&a1hi, g_a1hi);
    cudaGetSymbolAddress((void**)&a1lo, g_a1lo);

    cudaFuncSetAttribute(gemm_hmma<true, true, true>,
                         cudaFuncAttributeMaxDynamicSharedMemorySize, SMEM_B);
    cudaFuncSetAttribute(gemm_hmma<true, false, true>,
                         cudaFuncAttributeMaxDynamicSharedMemorySize, SMEM_B);
    cudaFuncSetAttribute(gemm_hmma<false, false, false>,
                         cudaFuncAttributeMaxDynamicSharedMemorySize, SMEM_B);

    // Pre-split operands to bf16 hi/lo (bandwidth-bound, ~310us total)
    const int SPLIT_GRID = 32 * 148;
    split_f32<<<SPLIT_GRID, 256>>>((const float4*)noisy, (uint2*)xhi,  (uint2*)xlo,
                                   (int)((size_t)BATCH * LATENT / 4));
    split_f32<<<SPLIT_GRID, 256>>>((const float4*)nw0,   (uint2*)w0hi, (uint2*)w0lo,
                                   (int)((size_t)HIDDEN * KIN / 4));
    split_f32<<<SPLIT_GRID, 256>>>((const float4*)nw1,   (uint2*)w1hi, (uint2*)w1lo,
                                   (int)((size_t)HIDDEN * HIDDEN / 4));
    split_f32<<<SPLIT_GRID, 256>>>((const float4*)nw2,   (uint2*)w2hi, (uint2*)w2lo,
                                   (int)((size_t)LATENT * HIDDEN / 4));
    prep_kernel<<<BATCH, 64>>>(timesteps, digits, num_steps, emb, tw0, tb0, tw1, tb1);

    // GEMM0: a0 = relu([x|tail] @ nw0^T + nb0)   M=4096 N=4096 K=20608
    gemm_hmma<true, true, true><<<(BATCH / 128) * (HIDDEN / 128), 128, SMEM_B>>>(
        xhi, xlo, thi, tlo, w0hi, w0lo, nb0,
        nullptr, a0hi, a0lo, BATCH, HIDDEN, KIN, LATENT, LATENT);

    // GEMM1: a1 = relu(a0 @ nw1^T + nb1)         M=4096 N=4096 K=4096
    gemm_hmma<true, false, true><<<(BATCH / 128) * (HIDDEN / 128), 128, SMEM_B>>>(
        a0hi, a0lo, nullptr, nullptr, w1hi, w1lo, nb1,
        nullptr, a1hi, a1lo, BATCH, HIDDEN, HIDDEN, HIDDEN, HIDDEN);

    // GEMM2: out = a1 @ nw2^T + nb2              M=4096 N=20480 K=4096
    gemm_hmma<false, false, false><<<(BATCH / 128) * (LATENT / 128), 128, SMEM_B>>>(
        a1hi, a1lo, nullptr, nullptr, w2hi, w2lo, nb2,
        out, nullptr, nullptr, BATCH, LATENT, HIDDEN, HIDDEN, HIDDEN);
}